// round 7
// baseline (speedup 1.0000x reference)
#include <cuda_runtime.h>
#include <cuda_bf16.h>

#define BATCH 32
#define KVH 8
#define G 4
#define HD 128
#define PS 16
#define L0P 256
#define L1P 64
#define L2P 32
#define ATT_SCALE 0.08838834764831845f

// Part A (level 0, shared prefix): 4 batch-groups x 8 kvh x 64 chunks (4 pages = 64 tok)
#define A_BG 4
#define A_BPG 8
#define A_CHP 4
#define A_NCH 64
#define A_BLOCKS (A_BG * KVH * A_NCH)          // 2048
// Part B (levels 1+2, per-seq): 32 b x 8 kvh x 6 chunks (16 pages = 256 tok)
#define B_CHP 16
#define B_NCH 6
#define B_BLOCKS (BATCH * KVH * B_NCH)         // 1536
#define NCH_TOT (A_NCH + B_NCH)                // 70 partials per (b,kvh)

// unnormalized partial sums (fixed m=0 softmax; merge = plain add)
__device__ float g_po[(size_t)BATCH * KVH * NCH_TOT * G * HD];
__device__ float g_pl[(size_t)BATCH * KVH * NCH_TOT * G];

union F2u { float2 f2; unsigned long long u; };
__device__ __forceinline__ float2 ffma2(float2 a, float2 b, float2 c) {
    F2u A, B, C, R; A.f2 = a; B.f2 = b; C.f2 = c;
    asm("fma.rn.f32x2 %0, %1, %2, %3;" : "=l"(R.u) : "l"(A.u), "l"(B.u), "l"(C.u));
    return R.f2;
}
__device__ __forceinline__ float2 fmul2(float2 a, float2 b) {
    F2u A, B, R; A.f2 = a; B.f2 = b;
    asm("mul.rn.f32x2 %0, %1, %2;" : "=l"(R.u) : "l"(A.u), "l"(B.u));
    return R.f2;
}

// reduce s[0..3] over the 16-lane half; ONE exp per lane (lane owns g=lane&3),
// broadcast e for all 4 g; lane adds only its own g's e into lpart.
// NOTE: lanes {x, x+4, x+8, x+12} end up with IDENTICAL lpart copies — the
// final cross-half combine must therefore be ONLY shfl_xor 16 (R5 bug: extra
// shfl 4/8 summed 4 identical copies -> L was 4x too large).
__device__ __forceinline__ void half_softmax(float s[4], int lane, float& lpart,
                                             float& e0, float& e1, float& e2, float& e3)
{
    #pragma unroll
    for (int off = 1; off <= 2; off <<= 1) {
        #pragma unroll
        for (int g = 0; g < 4; g++) s[g] += __shfl_xor_sync(0xffffffffu, s[g], off);
    }
    const int mg = lane & 3;
    float r = (mg == 0) ? s[0] : (mg == 1) ? s[1] : (mg == 2) ? s[2] : s[3];
    r += __shfl_xor_sync(0xffffffffu, r, 4);
    r += __shfl_xor_sync(0xffffffffu, r, 8);
    float e = __expf(r);
    lpart += e;
    const int base = lane & 16;
    e0 = __shfl_sync(0xffffffffu, e, base | 0);
    e1 = __shfl_sync(0xffffffffu, e, base | 1);
    e2 = __shfl_sync(0xffffffffu, e, base | 2);
    e3 = __shfl_sync(0xffffffffu, e, base | 3);
}

__global__ __launch_bounds__(256, 2)
void cascade_phase1(const float* __restrict__ q,
                    const float* __restrict__ kv,
                    const int* __restrict__ sp,
                    const int* __restrict__ p1,
                    const int* __restrict__ p2)
{
    __shared__ float sbuf[8192];
    __shared__ float s_l[8 * G];
    __shared__ int   pages_s[16];

    const int tid  = threadIdx.x;
    const int warp = tid >> 5;
    const int lane = tid & 31;
    const int half = lane >> 4;
    const int lr   = lane & 15;

    // interleave A:B = 4:3 so compute-bound A and DRAM-bound B co-execute
    const int bx   = blockIdx.x;
    const int grp  = bx / 7;
    const int rem  = bx - grp * 7;
    const bool isA = (rem < 4);

    const size_t KVROW = (size_t)KVH * HD;
    const size_t VOFF  = (size_t)PS * KVH * HD;
    const size_t PGSTR = 2 * VOFF;

    if (isA) {
        // ============ Part A: shared prefix, 8 batches per block ============
        const int a   = grp * 4 + rem;
        const int bg  = a & (A_BG - 1);
        const int kvh = (a >> 2) & (KVH - 1);
        const int ch  = a >> 5;
        const int b   = bg * A_BPG + warp;

        if (tid < A_CHP) pages_s[tid] = sp[ch * A_CHP + tid];

        float2 qr[G][4];
        {
            const float* qb = q + ((size_t)b * KVH + kvh) * G * HD;
            #pragma unroll
            for (int g = 0; g < G; g++) {
                float4 x = *(const float4*)(qb + g * HD + lr * 4);
                float4 y = *(const float4*)(qb + g * HD + 64 + lr * 4);
                qr[g][0] = make_float2(x.x * ATT_SCALE, x.y * ATT_SCALE);
                qr[g][1] = make_float2(x.z * ATT_SCALE, x.w * ATT_SCALE);
                qr[g][2] = make_float2(y.x * ATT_SCALE, y.y * ATT_SCALE);
                qr[g][3] = make_float2(y.z * ATT_SCALE, y.w * ATT_SCALE);
            }
        }
        __syncthreads();

        float lpart = 0.f;
        float2 acc[G][4];
        #pragma unroll
        for (int g = 0; g < G; g++)
            #pragma unroll
            for (int j = 0; j < 4; j++) acc[g][j] = make_float2(0.f, 0.f);

        float* sK = sbuf;
        float* sV = sbuf + 4096;

        auto load_tile = [&](int tt, int buf) {
            const int pg = pages_s[tt];
            const float* base = kv + (size_t)pg * PGSTR + (size_t)kvh * HD;
            #pragma unroll
            for (int j = 0; j < 2; j++) {
                int idx = tid + j * 256;
                int tp  = idx >> 5, seg = idx & 31;
                float4 kk = *(const float4*)(base + (size_t)tp * KVROW + seg * 4);
                float4 vv = *(const float4*)(base + VOFF + (size_t)tp * KVROW + seg * 4);
                *(float4*)(sK + buf * 2048 + tp * 128 + seg * 4) = kk;
                *(float4*)(sV + buf * 2048 + tp * 128 + seg * 4) = vv;
            }
        };

        load_tile(0, 0);
        __syncthreads();

        for (int tt = 0; tt < A_CHP; tt++) {
            if (tt + 1 < A_CHP) load_tile(tt + 1, (tt + 1) & 1);
            const int buf = tt & 1;
            #pragma unroll
            for (int it = 0; it < 16; it += 2) {
                const int tok = it + half;
                const float* kr = sK + buf * 2048 + tok * 128;
                const float* vr = sV + buf * 2048 + tok * 128;
                float4 k0 = *(const float4*)(kr + lr * 4);
                float4 k1 = *(const float4*)(kr + 64 + lr * 4);
                float4 v0 = *(const float4*)(vr + lr * 4);
                float4 v1 = *(const float4*)(vr + 64 + lr * 4);

                float2 kp[4] = { make_float2(k0.x,k0.y), make_float2(k0.z,k0.w),
                                 make_float2(k1.x,k1.y), make_float2(k1.z,k1.w) };
                float2 vp[4] = { make_float2(v0.x,v0.y), make_float2(v0.z,v0.w),
                                 make_float2(v1.x,v1.y), make_float2(v1.z,v1.w) };

                float s[G];
                #pragma unroll
                for (int g = 0; g < G; g++) {
                    float2 t = fmul2(qr[g][0], kp[0]);
                    t = ffma2(qr[g][1], kp[1], t);
                    t = ffma2(qr[g][2], kp[2], t);
                    t = ffma2(qr[g][3], kp[3], t);
                    s[g] = t.x + t.y;
                }
                float e0, e1, e2, e3;
                half_softmax(s, lane, lpart, e0, e1, e2, e3);
                #pragma unroll
                for (int j = 0; j < 4; j++) {
                    acc[0][j] = ffma2(make_float2(e0, e0), vp[j], acc[0][j]);
                    acc[1][j] = ffma2(make_float2(e1, e1), vp[j], acc[1][j]);
                    acc[2][j] = ffma2(make_float2(e2, e2), vp[j], acc[2][j]);
                    acc[3][j] = ffma2(make_float2(e3, e3), vp[j], acc[3][j]);
                }
            }
            __syncthreads();
        }

        // merge the two half-warp token-splits (lanes x,x+4,x+8,x+12 hold
        // identical lpart copies -> ONLY the cross-half shfl 16 for lpart)
        #pragma unroll
        for (int g = 0; g < G; g++)
            #pragma unroll
            for (int j = 0; j < 4; j++) {
                acc[g][j].x += __shfl_xor_sync(0xffffffffu, acc[g][j].x, 16);
                acc[g][j].y += __shfl_xor_sync(0xffffffffu, acc[g][j].y, 16);
            }
        lpart += __shfl_xor_sync(0xffffffffu, lpart, 16);
        // lanes 0..3 now hold l[g = lane]

        const size_t obase = (((size_t)b * KVH + kvh) * NCH_TOT + ch) * (size_t)(G * HD);
        const size_t lbase = (((size_t)b * KVH + kvh) * NCH_TOT + ch) * (size_t)G;
        if (half == 0) {
            #pragma unroll
            for (int g = 0; g < G; g++)
                #pragma unroll
                for (int j = 0; j < 4; j++) {
                    int d = (j < 2 ? 0 : 64) + lr * 4 + (j & 1) * 2;
                    *(float2*)(g_po + obase + g * HD + d) = acc[g][j];
                }
            if (lr < 4) g_pl[lbase + lr] = lpart;
        }
    } else {
        // ============ Part B: levels 1+2, per-sequence ============
        const int bidx = grp * 3 + (rem - 4);
        const int b    = bidx & (BATCH - 1);
        const int kvh  = (bidx >> 5) & (KVH - 1);
        const int ch   = bidx >> 8;

        if (tid < B_CHP) {
            int vp = ch * B_CHP + tid;
            pages_s[tid] = (vp < L1P) ? p1[b * L1P + vp] : p2[b * L2P + (vp - L1P)];
        }

        float2 qr[G][4];
        {
            const float* qb = q + ((size_t)b * KVH + kvh) * G * HD;
            #pragma unroll
            for (int g = 0; g < G; g++) {
                float4 x = *(const float4*)(qb + g * HD + lr * 4);
                float4 y = *(const float4*)(qb + g * HD + 64 + lr * 4);
                qr[g][0] = make_float2(x.x * ATT_SCALE, x.y * ATT_SCALE);
                qr[g][1] = make_float2(x.z * ATT_SCALE, x.w * ATT_SCALE);
                qr[g][2] = make_float2(y.x * ATT_SCALE, y.y * ATT_SCALE);
                qr[g][3] = make_float2(y.z * ATT_SCALE, y.w * ATT_SCALE);
            }
        }
        __syncthreads();

        float lpart = 0.f;
        float2 acc[G][4];
        #pragma unroll
        for (int g = 0; g < G; g++)
            #pragma unroll
            for (int j = 0; j < 4; j++) acc[g][j] = make_float2(0.f, 0.f);

        auto rowptr = [&](int tok) -> const float* {
            int pg = pages_s[tok >> 4];
            int tp = tok & 15;
            return kv + (size_t)pg * PGSTR + (size_t)tp * KVROW + (size_t)kvh * HD;
        };

        const int mytok = warp * 2 + half;
        const float* p = rowptr(mytok);
        float4 k0 = *(const float4*)(p + lr * 4);
        float4 k1 = *(const float4*)(p + 64 + lr * 4);
        float4 v0 = *(const float4*)(p + VOFF + lr * 4);
        float4 v1 = *(const float4*)(p + VOFF + 64 + lr * 4);

        for (int it = 16; it <= 256; it += 16) {
            float4 nk0, nk1, nv0, nv1;
            if (it < 256) {
                const float* np = rowptr(it + mytok);
                nk0 = *(const float4*)(np + lr * 4);
                nk1 = *(const float4*)(np + 64 + lr * 4);
                nv0 = *(const float4*)(np + VOFF + lr * 4);
                nv1 = *(const float4*)(np + VOFF + 64 + lr * 4);
            }

            float2 kp[4] = { make_float2(k0.x,k0.y), make_float2(k0.z,k0.w),
                             make_float2(k1.x,k1.y), make_float2(k1.z,k1.w) };
            float2 vp[4] = { make_float2(v0.x,v0.y), make_float2(v0.z,v0.w),
                             make_float2(v1.x,v1.y), make_float2(v1.z,v1.w) };

            float s[G];
            #pragma unroll
            for (int g = 0; g < G; g++) {
                float2 t = fmul2(qr[g][0], kp[0]);
                t = ffma2(qr[g][1], kp[1], t);
                t = ffma2(qr[g][2], kp[2], t);
                t = ffma2(qr[g][3], kp[3], t);
                s[g] = t.x + t.y;
            }
            float e0, e1, e2, e3;
            half_softmax(s, lane, lpart, e0, e1, e2, e3);
            #pragma unroll
            for (int j = 0; j < 4; j++) {
                acc[0][j] = ffma2(make_float2(e0, e0), vp[j], acc[0][j]);
                acc[1][j] = ffma2(make_float2(e1, e1), vp[j], acc[1][j]);
                acc[2][j] = ffma2(make_float2(e2, e2), vp[j], acc[2][j]);
                acc[3][j] = ffma2(make_float2(e3, e3), vp[j], acc[3][j]);
            }

            k0 = nk0; k1 = nk1; v0 = nv0; v1 = nv1;
        }

        // merge halves (lpart: ONLY shfl 16 — see half_softmax note)
        #pragma unroll
        for (int g = 0; g < G; g++)
            #pragma unroll
            for (int j = 0; j < 4; j++) {
                acc[g][j].x += __shfl_xor_sync(0xffffffffu, acc[g][j].x, 16);
                acc[g][j].y += __shfl_xor_sync(0xffffffffu, acc[g][j].y, 16);
            }
        lpart += __shfl_xor_sync(0xffffffffu, lpart, 16);

        if (half == 0) {
            #pragma unroll
            for (int g = 0; g < G; g++)
                #pragma unroll
                for (int j = 0; j < 4; j++) {
                    int d = (j < 2 ? 0 : 64) + lr * 4 + (j & 1) * 2;
                    *(float2*)(sbuf + warp * 512 + g * HD + d) = acc[g][j];
                }
            if (lr < 4) s_l[warp * G + lr] = lpart;
        }
        __syncthreads();

        const size_t obase = (((size_t)b * KVH + kvh) * NCH_TOT + (A_NCH + ch)) * (size_t)(G * HD);
        const size_t lbase = (((size_t)b * KVH + kvh) * NCH_TOT + (A_NCH + ch)) * (size_t)G;
        #pragma unroll
        for (int pidx = 0; pidx < 2; pidx++) {
            int p2i = tid + pidx * 256;
            float O = 0.f;
            #pragma unroll
            for (int w = 0; w < 8; w++) O += sbuf[w * 512 + p2i];
            g_po[obase + p2i] = O;
        }
        if (tid < G) {
            float L = 0.f;
            #pragma unroll
            for (int w = 0; w < 8; w++) L += s_l[w * G + tid];
            g_pl[lbase + tid] = L;
        }
    }
}

__global__ __launch_bounds__(128)
void cascade_phase2(float* __restrict__ out)
{
    const int b   = blockIdx.x;
    const int kvh = blockIdx.y;
    const int g   = threadIdx.x >> 5;     // 0..3
    const int d4  = threadIdx.x & 31;     // float4 slot 0..31

    __shared__ float spl[NCH_TOT * G];
    for (int i = threadIdx.x; i < NCH_TOT * G; i += 128)
        spl[i] = g_pl[((size_t)b * KVH + kvh) * NCH_TOT * G + i];
    __syncthreads();

    float L = 0.f;
    #pragma unroll
    for (int ch = 0; ch < NCH_TOT; ch++) L += spl[ch * G + g];
    const float inv = 1.f / L;

    const float* pb = g_po + ((size_t)b * KVH + kvh) * NCH_TOT * (size_t)(G * HD)
                           + (size_t)g * HD + d4 * 4;
    float4 O = make_float4(0.f, 0.f, 0.f, 0.f);
    #pragma unroll 14
    for (int ch = 0; ch < NCH_TOT; ch++) {
        float4 v = *(const float4*)(pb + (size_t)ch * (G * HD));
        O.x += v.x; O.y += v.y; O.z += v.z; O.w += v.w;
    }
    O.x *= inv; O.y *= inv; O.z *= inv; O.w *= inv;
    *(float4*)(out + ((size_t)b * KVH + kvh) * G * HD + (size_t)g * HD + d4 * 4) = O;
}

extern "C" void kernel_launch(void* const* d_in, const int* in_sizes, int n_in,
                              void* d_out, int out_size)
{
    const float* q  = (const float*)d_in[0];
    const float* kv = (const float*)d_in[1];
    const int*   sp = (const int*)d_in[2];
    const int*   p1 = (const int*)d_in[3];
    const int*   p2 = (const int*)d_in[4];
    float* out = (float*)d_out;

    cascade_phase1<<<A_BLOCKS + B_BLOCKS, 256>>>(q, kv, sp, p1, p2);
    cascade_phase2<<<dim3(BATCH, KVH), 128>>>(out);
}